// round 10
// baseline (speedup 1.0000x reference)
#include <cuda_runtime.h>
#include <cstdint>

// ---------------------------------------------------------------------------
// Scratch
// ---------------------------------------------------------------------------
__device__ int    g_fps_idx[8 * 4096];
__device__ float4 g_sorted[8 * 8192];     // per-batch spatially sorted points

typedef unsigned long long u64;

// ---------------------------------------------------------------------------
// Helpers
// ---------------------------------------------------------------------------
__device__ __forceinline__ uint32_t smem_u32(const void* p) {
    uint32_t a;
    asm("{ .reg .u64 t; cvta.to.shared.u64 t, %1; cvt.u32.u64 %0, t; }"
        : "=r"(a) : "l"(p));
    return a;
}
__device__ __forceinline__ u64 lds_vol_u64(const u64* p) {
    u64 v;
    asm volatile("ld.volatile.shared.b64 %0, [%1];" : "=l"(v) : "r"(smem_u32(p)));
    return v;
}
__device__ __forceinline__ void sts_vol_u64(u64* p, u64 v) {
    asm volatile("st.volatile.shared.b64 [%0], %1;" :: "r"(smem_u32(p)), "l"(v) : "memory");
}

// Packed f32x2 add (per-lane IEEE rn — proven bitwise == scalar FADD in R6)
__device__ __forceinline__ u64 pack2(float a, float b) {
    u64 r; asm("mov.b64 %0, {%1, %2};" : "=l"(r) : "f"(a), "f"(b)); return r;
}
__device__ __forceinline__ void unpack2(u64 v, float& a, float& b) {
    asm("mov.b64 {%0, %1}, %2;" : "=f"(a), "=f"(b) : "l"(v));
}
__device__ __forceinline__ u64 add2(u64 a, u64 b) {
    u64 r; asm("add.rn.f32x2 %0, %1, %2;" : "=l"(r) : "l"(a), "l"(b)); return r;
}

// 8x8x8 Morton cell over [-4, 4]
__device__ __forceinline__ int cell_of(float x, float y, float z) {
    int cx = min(max((int)(x + 4.0f), 0), 7);
    int cy = min(max((int)(y + 4.0f), 0), 7);
    int cz = min(max((int)(z + 4.0f), 0), 7);
    return (cx & 1) | ((cy & 1) << 1) | ((cz & 1) << 2)
         | (((cx >> 1) & 1) << 3) | (((cy >> 1) & 1) << 4) | (((cz >> 1) & 1) << 5)
         | ((cx >> 2) << 6) | ((cy >> 2) << 7) | ((cz >> 2) << 8);
}

// Dummy kernel: keeps ncu's fixed capture slot on fps_kernel<4096,4>.
__global__ void probe_align_kernel() {}

// ---------------------------------------------------------------------------
// FPS with per-warp bbox pruning and a BARRIER-FREE iteration skeleton.
//
// Per iteration each warp's lane 0 publishes a tagged key into a parity
// double-buffered smem mailbox:
//     key = (cm << 32) | (comp13 << 12) | tag
//     cm     = warp max distance bits (>=0 -> bit order == value order)
//     comp13 = 8191 - orig_idx of the warp argmax (max => min index on ties
//              -> exact jnp.argmax first-occurrence)
//     tag    = iteration (12 bits; npoints <= 4096 so tags are unique)
// Every warp spins on ONE volatile LDS.64 per lane until all 32 tags match
// (__all_sync), then stage-2 redux picks the winner. No __syncthreads in
// the loop. Parity safety: a warp writes slot p for it+1 only after
// consuming all keys of it, which required every warp to have consumed
// it-1 (same proof as the R5 cluster mailbox). Zero-init beats garbage.
//
// Active path (packed-add + verbatim scalar squared-sum) and the exact
// monotonicity-based bbox skip are unchanged from R8/R9.
// ---------------------------------------------------------------------------
template <int N, int K>
__global__ __launch_bounds__(1024, 1)
void fps_kernel(const float* __restrict__ pts, int C, int npoints,
                int* __restrict__ idx_out, float4* __restrict__ sorted_g)
{
    extern __shared__ float4 sxyz[];          // N entries, ORIGINAL order
    __shared__ u64 kkey[2][32];               // tagged parity mailboxes
    __shared__ int hist[512];
    __shared__ int offs[512];

    const int b    = blockIdx.x;
    const int t    = threadIdx.x;
    const int lane = t & 31;
    const int wid  = t >> 5;

    const float* base = pts + (size_t)b * N * C;
    float4* sorted = sorted_g + (size_t)b * N;

    // ---- init mailboxes + histogram ----
    if (t < 64) ((u64*)kkey)[t] = 0;          // tag 0 never matches (it>=1)
    if (t < 512) hist[t] = 0;
    __syncthreads();
#pragma unroll
    for (int k = 0; k < K; ++k) {
        int i = t + k * 1024;
        const float* r = base + (size_t)i * C;
        float xx = r[0], yy = r[1], zz = r[2];
        sxyz[i] = make_float4(xx, yy, zz, 0.f);
        atomicAdd(&hist[cell_of(xx, yy, zz)], 1);
    }
    __syncthreads();
    if (t == 0) {
        int s = 0;
        for (int c = 0; c < 512; ++c) { offs[c] = s; s += hist[c]; }
    }
    __syncthreads();
#pragma unroll
    for (int k = 0; k < K; ++k) {
        int i = t + k * 1024;
        float4 q = sxyz[i];
        int pos = atomicAdd(&offs[cell_of(q.x, q.y, q.z)], 1);
        sorted[pos] = make_float4(q.x, q.y, q.z, __int_as_float(i));
    }
    __syncthreads();

    // ---- load my sorted points ----
    float xr[K], yr[K], zr[K], d[K];
    unsigned comp[K];                         // 8191 - orig_idx (13 bits)
#pragma unroll
    for (int k = 0; k < K; ++k) {
        int slot = wid * (32 * K) + k * 32 + lane;
        float4 s = sorted[slot];
        xr[k] = s.x; yr[k] = s.y; zr[k] = s.z;
        comp[k] = 8191u - (unsigned)__float_as_int(s.w);
    }

    // ---- per-thread insertion sort by orig idx ascending ----
    if constexpr (K >= 2) {
#pragma unroll
        for (int a = 1; a < K; ++a) {
#pragma unroll
            for (int c = a; c > 0; --c) {
                bool sw = comp[c] > comp[c - 1];
                float tf; unsigned tu;
                tf = sw ? xr[c] : xr[c - 1]; xr[c] = sw ? xr[c - 1] : xr[c]; xr[c - 1] = tf;
                tf = sw ? yr[c] : yr[c - 1]; yr[c] = sw ? yr[c - 1] : yr[c]; yr[c - 1] = tf;
                tf = sw ? zr[c] : zr[c - 1]; zr[c] = sw ? zr[c - 1] : zr[c]; zr[c - 1] = tf;
                tu = sw ? comp[c] : comp[c - 1]; comp[c] = sw ? comp[c - 1] : comp[c]; comp[c - 1] = tu;
            }
        }
    }

    // ---- per-warp bbox ----
    float mnx = 1e30f, mny = 1e30f, mnz = 1e30f;
    float mxx = -1e30f, mxy = -1e30f, mxz = -1e30f;
#pragma unroll
    for (int k = 0; k < K; ++k) {
        mnx = fminf(mnx, xr[k]); mxx = fmaxf(mxx, xr[k]);
        mny = fminf(mny, yr[k]); mxy = fmaxf(mxy, yr[k]);
        mnz = fminf(mnz, zr[k]); mxz = fmaxf(mxz, zr[k]);
    }
#pragma unroll
    for (int o = 16; o > 0; o >>= 1) {
        mnx = fminf(mnx, __shfl_xor_sync(0xffffffffu, mnx, o));
        mny = fminf(mny, __shfl_xor_sync(0xffffffffu, mny, o));
        mnz = fminf(mnz, __shfl_xor_sync(0xffffffffu, mnz, o));
        mxx = fmaxf(mxx, __shfl_xor_sync(0xffffffffu, mxx, o));
        mxy = fmaxf(mxy, __shfl_xor_sync(0xffffffffu, mxy, o));
        mxz = fmaxf(mxz, __shfl_xor_sync(0xffffffffu, mxz, o));
    }

    // ---- packed coord registers (K>=2) ----
    constexpr int KP = (K >= 2) ? K / 2 : 1;
    u64 xp[KP], yp[KP], zp[KP];
    if constexpr (K >= 2) {
#pragma unroll
        for (int k2 = 0; k2 < KP; ++k2) {
            xp[k2] = pack2(xr[2 * k2], xr[2 * k2 + 1]);
            yp[k2] = pack2(yr[2 * k2], yr[2 * k2 + 1]);
            zp[k2] = pack2(zr[2 * k2], zr[2 * k2 + 1]);
        }
    }

    if (t == 0) idx_out[b * npoints] = 0;

    // ---- initial distances to point 0 + argmax ----
    float    bv = -1.0f;
    unsigned bc = 0;
    {
        float4 q = sxyz[0];
        float px = q.x, py = q.y, pz = q.z;
#pragma unroll
        for (int k = 0; k < K; ++k) {
            float dx = xr[k] - px, dy = yr[k] - py, dz = zr[k] - pz;
            d[k] = dx * dx + dy * dy + dz * dz;
            if (d[k] > bv) { bv = d[k]; bc = comp[k]; }
        }
    }
    unsigned cm, ccomp;
    {
        unsigned ub = __float_as_uint(bv);
        cm = __reduce_max_sync(0xffffffffu, ub);
        unsigned cand = (ub == cm) ? bc : 0u;
        ccomp = __reduce_max_sync(0xffffffffu, cand);
    }

    for (int it = 1; it < npoints; ++it) {
        const int p = it & 1;
        const unsigned tag = (unsigned)it & 0xFFFu;

        // publish this warp's tagged key
        if (lane == 0)
            sts_vol_u64(&kkey[p][wid],
                        ((u64)cm << 32) | ((u64)ccomp << 12) | (u64)tag);

        // spin: one volatile LDS.64 per lane until all 32 tags match
        u64 kk;
        do {
            kk = lds_vol_u64(&kkey[p][lane]);
        } while (!__all_sync(0xffffffffu, ((unsigned)kk & 0xFFFu) == tag));

        // stage 2: reduce the 32 keys
        unsigned vw = (unsigned)(kk >> 32);
        unsigned iw = (unsigned)(kk >> 12) & 0x1FFFu;
        unsigned m2 = __reduce_max_sync(0xffffffffu, vw);
        unsigned c2 = (vw == m2) ? iw : 0u;
        unsigned comp2 = __reduce_max_sync(0xffffffffu, c2);
        int bsel = 8191 - (int)comp2;               // ORIGINAL index

        if (t == 0) idx_out[b * npoints + it] = bsel;

        float4 q = sxyz[bsel];
        float px = q.x, py = q.y, pz = q.z;

        // warp-uniform exact bbox skip test
        float ax = fmaxf(fmaxf(mnx - px, px - mxx), 0.f);
        float ay = fmaxf(fmaxf(mny - py, py - mxy), 0.f);
        float az = fmaxf(fmaxf(mnz - pz, pz - mxz), 0.f);
        float mind2 = ax * ax + ay * ay + az * az;

        if (mind2 < __uint_as_float(cm)) {
            bv = -1.0f; bc = 0;
            if constexpr (K >= 2) {
                const u64 nxp = pack2(-px, -px);
                const u64 nyp = pack2(-py, -py);
                const u64 nzp = pack2(-pz, -pz);
#pragma unroll
                for (int k2 = 0; k2 < KP; ++k2) {
                    float dx0, dx1, dy0, dy1, dz0, dz1;
                    unpack2(add2(xp[k2], nxp), dx0, dx1);
                    unpack2(add2(yp[k2], nyp), dy0, dy1);
                    unpack2(add2(zp[k2], nzp), dz0, dz1);
                    float nd0 = dx0 * dx0 + dy0 * dy0 + dz0 * dz0;
                    float nd1 = dx1 * dx1 + dy1 * dy1 + dz1 * dz1;
                    float dk0 = fminf(d[2 * k2],     nd0);
                    float dk1 = fminf(d[2 * k2 + 1], nd1);
                    d[2 * k2]     = dk0;
                    d[2 * k2 + 1] = dk1;
                    if (dk0 > bv) { bv = dk0; bc = comp[2 * k2]; }
                    if (dk1 > bv) { bv = dk1; bc = comp[2 * k2 + 1]; }
                }
            } else {
                float dx = xr[0] - px, dy = yr[0] - py, dz = zr[0] - pz;
                float nd = dx * dx + dy * dy + dz * dz;
                float dk = fminf(d[0], nd);
                d[0] = dk; bv = dk; bc = comp[0];
            }
            unsigned ub = __float_as_uint(bv);
            cm = __reduce_max_sync(0xffffffffu, ub);
            unsigned cand = (ub == cm) ? bc : 0u;
            ccomp = __reduce_max_sync(0xffffffffu, cand);
        }
        // else: skip — d unchanged, cached (cm, ccomp) still exact
    }
}

// ---------------------------------------------------------------------------
// Gather + pointwise 2-layer MLP + output assembly (unchanged).
// ---------------------------------------------------------------------------
template <int CPREV, int F, bool REPEAT>
__global__ __launch_bounds__(256)
void mlp_kernel(const float* __restrict__ in, const int* __restrict__ idx,
                const float* __restrict__ w1, const float* __restrict__ b1,
                const float* __restrict__ w2, const float* __restrict__ b2,
                float* __restrict__ out, int n_in, int npoints)
{
    constexpr int PPB = 256 / F;
    constexpr int CIN = REPEAT ? 2 * CPREV : CPREV;

    __shared__ float row[PPB][CPREV];
    __shared__ float hsm[PPB][F];

    const int t  = threadIdx.x;
    const int lp = t / F;
    const int g  = t % F;
    const int gp = blockIdx.x * PPB + lp;
    const int b  = gp / npoints;
    const int pt = gp % npoints;

    const int src = idx[b * npoints + pt];
    const float* r = in + ((size_t)b * n_in + src) * CPREV;
    if (g < CPREV) row[lp][g] = r[g];
    __syncthreads();

    float acc = b1[g];
#pragma unroll
    for (int c = 0; c < CIN; ++c)
        acc += row[lp][c % CPREV] * w1[c * F + g];
    hsm[lp][g] = fmaxf(acc, 0.0f);
    __syncthreads();

    float o = b2[g];
#pragma unroll
    for (int j = 0; j < F; ++j)
        o += hsm[lp][j] * w2[j * F + g];

    float* orow = out + ((size_t)b * npoints + pt) * F;
    orow[g] = (g < 3) ? row[lp][g] : o;
}

// ---------------------------------------------------------------------------
// Launch
// ---------------------------------------------------------------------------
extern "C" void kernel_launch(void* const* d_in, const int* in_sizes, int n_in_cnt,
                              void* d_out, int out_size)
{
    (void)in_sizes; (void)n_in_cnt; (void)out_size;

    const float* pts  = (const float*)d_in[0];
    const float* w1_1 = (const float*)d_in[1];
    const float* b1_1 = (const float*)d_in[2];
    const float* w2_1 = (const float*)d_in[3];
    const float* b2_1 = (const float*)d_in[4];
    const float* w1_2 = (const float*)d_in[5];
    const float* b1_2 = (const float*)d_in[6];
    const float* w2_2 = (const float*)d_in[7];
    const float* b2_2 = (const float*)d_in[8];
    const float* w1_3 = (const float*)d_in[9];
    const float* b1_3 = (const float*)d_in[10];
    const float* w2_3 = (const float*)d_in[11];
    const float* b2_3 = (const float*)d_in[12];
    const float* w1_4 = (const float*)d_in[13];
    const float* b1_4 = (const float*)d_in[14];
    const float* w2_4 = (const float*)d_in[15];
    const float* b2_4 = (const float*)d_in[16];

    float* out = (float*)d_out;
    const int B = 8;
    float* f1 = out;                        // [8,4096,16]
    float* f2 = out + 8 * 4096 * 16;        // [8,2048,32]
    float* f3 = f2 + 8 * 2048 * 32;         // [8,1024,64]
    float* f4 = f3 + 8 * 1024 * 64;         // [8, 512,128]

    static int*    idx_buf = nullptr;
    static float4* sort_buf = nullptr;
    if (!idx_buf)  cudaGetSymbolAddress((void**)&idx_buf,  g_fps_idx);
    if (!sort_buf) cudaGetSymbolAddress((void**)&sort_buf, g_sorted);

    static bool attr_done = false;
    if (!attr_done) {
        cudaFuncSetAttribute(fps_kernel<8192, 8>,
                             cudaFuncAttributeMaxDynamicSharedMemorySize, 8192 * 16);
        cudaFuncSetAttribute(fps_kernel<4096, 4>,
                             cudaFuncAttributeMaxDynamicSharedMemorySize, 4096 * 16);
        cudaFuncSetAttribute(fps_kernel<2048, 2>,
                             cudaFuncAttributeMaxDynamicSharedMemorySize, 2048 * 16);
        cudaFuncSetAttribute(fps_kernel<1024, 1>,
                             cudaFuncAttributeMaxDynamicSharedMemorySize, 1024 * 16);
        attr_done = true;
    }

    // Slot shim: keeps ncu's fixed capture index on fps_kernel<4096,4>.
    probe_align_kernel<<<1, 32>>>();

    // ---- Level 1: 8192 -> 4096, C=3 (repeat to 6), F=16 ----
    fps_kernel<8192, 8><<<B, 1024, 8192 * 16>>>(pts, 3, 4096, idx_buf, sort_buf);
    mlp_kernel<3, 16, true><<<(B * 4096) / 16, 256>>>(
        pts, idx_buf, w1_1, b1_1, w2_1, b2_1, f1, 8192, 4096);

    // ---- Level 2: 4096 -> 2048, C=16, F=32 ----
    fps_kernel<4096, 4><<<B, 1024, 4096 * 16>>>(f1, 16, 2048, idx_buf, sort_buf);
    mlp_kernel<16, 32, false><<<(B * 2048) / 8, 256>>>(
        f1, idx_buf, w1_2, b1_2, w2_2, b2_2, f2, 4096, 2048);

    // ---- Level 3: 2048 -> 1024, C=32, F=64 ----
    fps_kernel<2048, 2><<<B, 1024, 2048 * 16>>>(f2, 32, 1024, idx_buf, sort_buf);
    mlp_kernel<32, 64, false><<<(B * 1024) / 4, 256>>>(
        f2, idx_buf, w1_3, b1_3, w2_3, b2_3, f3, 2048, 1024);

    // ---- Level 4: 1024 -> 512, C=64, F=128 ----
    fps_kernel<1024, 1><<<B, 1024, 1024 * 16>>>(f3, 64, 512, idx_buf, sort_buf);
    mlp_kernel<64, 128, false><<<(B * 512) / 2, 256>>>(
        f3, idx_buf, w1_4, b1_4, w2_4, b2_4, f4, 1024, 512);
}

// round 11
// speedup vs baseline: 1.8222x; 1.8222x over previous
#include <cuda_runtime.h>
#include <cstdint>

// ---------------------------------------------------------------------------
// Scratch
// ---------------------------------------------------------------------------
__device__ int    g_fps_idx[8 * 4096];
__device__ float4 g_sorted[8 * 8192];     // per-batch spatially sorted points

typedef unsigned long long u64;

// Packed f32x2 add (per-lane IEEE rn — proven bitwise == scalar FADD in R6)
__device__ __forceinline__ u64 pack2(float a, float b) {
    u64 r; asm("mov.b64 %0, {%1, %2};" : "=l"(r) : "f"(a), "f"(b)); return r;
}
__device__ __forceinline__ void unpack2(u64 v, float& a, float& b) {
    asm("mov.b64 {%0, %1}, %2;" : "=f"(a), "=f"(b) : "l"(v));
}
__device__ __forceinline__ u64 add2(u64 a, u64 b) {
    u64 r; asm("add.rn.f32x2 %0, %1, %2;" : "=l"(r) : "l"(a), "l"(b)); return r;
}

// 8x8x8 Morton cell over [-4, 4]
__device__ __forceinline__ int cell_of(float x, float y, float z) {
    int cx = min(max((int)(x + 4.0f), 0), 7);
    int cy = min(max((int)(y + 4.0f), 0), 7);
    int cz = min(max((int)(z + 4.0f), 0), 7);
    return (cx & 1) | ((cy & 1) << 1) | ((cz & 1) << 2)
         | (((cx >> 1) & 1) << 3) | (((cy >> 1) & 1) << 4) | (((cz >> 1) & 1) << 5)
         | ((cx >> 2) << 6) | ((cy >> 2) << 7) | ((cz >> 2) << 8);
}

// Dummy kernel: keeps ncu's fixed capture slot on the level-2 FPS launch.
__global__ void probe_align_kernel() {}

// ---------------------------------------------------------------------------
// FPS, 512 threads (16 warps) per batch — R9 skeleton (BAR.SYNC + packed
// u64 warp keys + redux) with half the warps. Skeleton issue cost per
// iteration is linear in warp count (measured R9: fma 1.8%, issue 70% ->
// pure skeleton), so 16 warps ~ halves it. K doubles; the update loop is
// mostly eliminated by the exact per-warp bbox prune, so the extra per-warp
// points are nearly free.
//
// All numerics (packed-add subtraction == scalar FADD, verbatim scalar
// squared-sum contraction, redux value/complement tie-break == jnp.argmax,
// monotonicity-exact skip test) are unchanged from the bit-proven R9.
// ---------------------------------------------------------------------------
template <int N, int K>
__global__ __launch_bounds__(512, 1)
void fps_kernel(const float* __restrict__ pts, int C, int npoints,
                int* __restrict__ idx_out, float4* __restrict__ sorted_g)
{
    constexpr int T  = 512;                   // threads
    constexpr int NW = 16;                    // warps

    extern __shared__ float4 sxyz[];          // N entries, ORIGINAL order
    __shared__ u64 rkey[2][NW];               // packed (valbits<<32)|comp
    __shared__ int hist[512];
    __shared__ int offs[512];

    const int b    = blockIdx.x;
    const int t    = threadIdx.x;
    const int lane = t & 31;
    const int wid  = t >> 5;

    const float* base = pts + (size_t)b * N * C;
    float4* sorted = sorted_g + (size_t)b * N;

    // ---- load orig-order copy + cell histogram ----
    hist[t] = 0;
    __syncthreads();
#pragma unroll
    for (int k = 0; k < K; ++k) {
        int i = t + k * T;
        const float* r = base + (size_t)i * C;
        float xx = r[0], yy = r[1], zz = r[2];
        sxyz[i] = make_float4(xx, yy, zz, 0.f);
        atomicAdd(&hist[cell_of(xx, yy, zz)], 1);
    }
    __syncthreads();
    if (t == 0) {
        int s = 0;
        for (int c = 0; c < 512; ++c) { offs[c] = s; s += hist[c]; }
    }
    __syncthreads();
#pragma unroll
    for (int k = 0; k < K; ++k) {
        int i = t + k * T;
        float4 q = sxyz[i];
        int pos = atomicAdd(&offs[cell_of(q.x, q.y, q.z)], 1);
        sorted[pos] = make_float4(q.x, q.y, q.z, __int_as_float(i));
    }
    __syncthreads();

    // ---- load my sorted points ----
    float xr[K], yr[K], zr[K], d[K];
    unsigned comp[K];                         // 0xFFFFFFFF - orig_idx
#pragma unroll
    for (int k = 0; k < K; ++k) {
        int slot = wid * (32 * K) + k * 32 + lane;
        float4 s = sorted[slot];
        xr[k] = s.x; yr[k] = s.y; zr[k] = s.z;
        comp[k] = 0xFFFFFFFFu - (unsigned)__float_as_int(s.w);
    }

    // ---- per-thread insertion sort by orig idx ascending (one-time) ----
    if constexpr (K >= 2) {
#pragma unroll
        for (int a = 1; a < K; ++a) {
#pragma unroll
            for (int c = a; c > 0; --c) {
                bool sw = comp[c] > comp[c - 1];
                float tf; unsigned tu;
                tf = sw ? xr[c] : xr[c - 1]; xr[c] = sw ? xr[c - 1] : xr[c]; xr[c - 1] = tf;
                tf = sw ? yr[c] : yr[c - 1]; yr[c] = sw ? yr[c - 1] : yr[c]; yr[c - 1] = tf;
                tf = sw ? zr[c] : zr[c - 1]; zr[c] = sw ? zr[c - 1] : zr[c]; zr[c - 1] = tf;
                tu = sw ? comp[c] : comp[c - 1]; comp[c] = sw ? comp[c - 1] : comp[c]; comp[c - 1] = tu;
            }
        }
    }

    // ---- per-warp bbox ----
    float mnx = 1e30f, mny = 1e30f, mnz = 1e30f;
    float mxx = -1e30f, mxy = -1e30f, mxz = -1e30f;
#pragma unroll
    for (int k = 0; k < K; ++k) {
        mnx = fminf(mnx, xr[k]); mxx = fmaxf(mxx, xr[k]);
        mny = fminf(mny, yr[k]); mxy = fmaxf(mxy, yr[k]);
        mnz = fminf(mnz, zr[k]); mxz = fmaxf(mxz, zr[k]);
    }
#pragma unroll
    for (int o = 16; o > 0; o >>= 1) {
        mnx = fminf(mnx, __shfl_xor_sync(0xffffffffu, mnx, o));
        mny = fminf(mny, __shfl_xor_sync(0xffffffffu, mny, o));
        mnz = fminf(mnz, __shfl_xor_sync(0xffffffffu, mnz, o));
        mxx = fmaxf(mxx, __shfl_xor_sync(0xffffffffu, mxx, o));
        mxy = fmaxf(mxy, __shfl_xor_sync(0xffffffffu, mxy, o));
        mxz = fmaxf(mxz, __shfl_xor_sync(0xffffffffu, mxz, o));
    }

    // ---- packed coord registers (K>=2) ----
    constexpr int KP = (K >= 2) ? K / 2 : 1;
    u64 xp[KP], yp[KP], zp[KP];
    if constexpr (K >= 2) {
#pragma unroll
        for (int k2 = 0; k2 < KP; ++k2) {
            xp[k2] = pack2(xr[2 * k2], xr[2 * k2 + 1]);
            yp[k2] = pack2(yr[2 * k2], yr[2 * k2 + 1]);
            zp[k2] = pack2(zr[2 * k2], zr[2 * k2 + 1]);
        }
    }

    if (t == 0) idx_out[b * npoints] = 0;

    // ---- initial distances to point 0 + argmax ----
    float    bv = -1.0f;
    unsigned bc = 0;
    {
        float4 q = sxyz[0];
        float px = q.x, py = q.y, pz = q.z;
#pragma unroll
        for (int k = 0; k < K; ++k) {
            float dx = xr[k] - px, dy = yr[k] - py, dz = zr[k] - pz;
            d[k] = dx * dx + dy * dy + dz * dz;
            if (d[k] > bv) { bv = d[k]; bc = comp[k]; }
        }
    }
    unsigned cm, ccomp;
    {
        unsigned ub = __float_as_uint(bv);
        cm = __reduce_max_sync(0xffffffffu, ub);
        unsigned cand = (ub == cm) ? bc : 0u;
        ccomp = __reduce_max_sync(0xffffffffu, cand);
    }

    for (int it = 1; it < npoints; ++it) {
        const int p = it & 1;
        if (lane == 0) rkey[p][wid] = ((u64)cm << 32) | (u64)ccomp;
        __syncthreads();

        // stage 2: reduce the 16 warp keys (lanes 16..31 read duplicates —
        // harmless under max)
        u64 kk = rkey[p][lane & (NW - 1)];
        unsigned vw = (unsigned)(kk >> 32);
        unsigned iw = (unsigned)kk;
        unsigned m2 = __reduce_max_sync(0xffffffffu, vw);
        unsigned c2 = (vw == m2) ? iw : 0u;
        unsigned comp2 = __reduce_max_sync(0xffffffffu, c2);
        int bsel = (int)(0xFFFFFFFFu - comp2);       // ORIGINAL index

        if (t == 0) idx_out[b * npoints + it] = bsel;

        float4 q = sxyz[bsel];
        float px = q.x, py = q.y, pz = q.z;

        // warp-uniform exact bbox skip test
        float ax = fmaxf(fmaxf(mnx - px, px - mxx), 0.f);
        float ay = fmaxf(fmaxf(mny - py, py - mxy), 0.f);
        float az = fmaxf(fmaxf(mnz - pz, pz - mxz), 0.f);
        float mind2 = ax * ax + ay * ay + az * az;

        if (mind2 < __uint_as_float(cm)) {
            bv = -1.0f; bc = 0;
            if constexpr (K >= 2) {
                const u64 nxp = pack2(-px, -px);
                const u64 nyp = pack2(-py, -py);
                const u64 nzp = pack2(-pz, -pz);
#pragma unroll
                for (int k2 = 0; k2 < KP; ++k2) {
                    float dx0, dx1, dy0, dy1, dz0, dz1;
                    unpack2(add2(xp[k2], nxp), dx0, dx1);
                    unpack2(add2(yp[k2], nyp), dy0, dy1);
                    unpack2(add2(zp[k2], nzp), dz0, dz1);
                    float nd0 = dx0 * dx0 + dy0 * dy0 + dz0 * dz0;
                    float nd1 = dx1 * dx1 + dy1 * dy1 + dz1 * dz1;
                    float dk0 = fminf(d[2 * k2],     nd0);
                    float dk1 = fminf(d[2 * k2 + 1], nd1);
                    d[2 * k2]     = dk0;
                    d[2 * k2 + 1] = dk1;
                    if (dk0 > bv) { bv = dk0; bc = comp[2 * k2]; }
                    if (dk1 > bv) { bv = dk1; bc = comp[2 * k2 + 1]; }
                }
            } else {
                float dx = xr[0] - px, dy = yr[0] - py, dz = zr[0] - pz;
                float nd = dx * dx + dy * dy + dz * dz;
                float dk = fminf(d[0], nd);
                d[0] = dk; bv = dk; bc = comp[0];
            }
            unsigned ub = __float_as_uint(bv);
            cm = __reduce_max_sync(0xffffffffu, ub);
            unsigned cand = (ub == cm) ? bc : 0u;
            ccomp = __reduce_max_sync(0xffffffffu, cand);
        }
        // else: skip — d unchanged, cached (cm, ccomp) still exact
    }
}

// ---------------------------------------------------------------------------
// Gather + pointwise 2-layer MLP + output assembly (unchanged).
// ---------------------------------------------------------------------------
template <int CPREV, int F, bool REPEAT>
__global__ __launch_bounds__(256)
void mlp_kernel(const float* __restrict__ in, const int* __restrict__ idx,
                const float* __restrict__ w1, const float* __restrict__ b1,
                const float* __restrict__ w2, const float* __restrict__ b2,
                float* __restrict__ out, int n_in, int npoints)
{
    constexpr int PPB = 256 / F;
    constexpr int CIN = REPEAT ? 2 * CPREV : CPREV;

    __shared__ float row[PPB][CPREV];
    __shared__ float hsm[PPB][F];

    const int t  = threadIdx.x;
    const int lp = t / F;
    const int g  = t % F;
    const int gp = blockIdx.x * PPB + lp;
    const int b  = gp / npoints;
    const int pt = gp % npoints;

    const int src = idx[b * npoints + pt];
    const float* r = in + ((size_t)b * n_in + src) * CPREV;
    if (g < CPREV) row[lp][g] = r[g];
    __syncthreads();

    float acc = b1[g];
#pragma unroll
    for (int c = 0; c < CIN; ++c)
        acc += row[lp][c % CPREV] * w1[c * F + g];
    hsm[lp][g] = fmaxf(acc, 0.0f);
    __syncthreads();

    float o = b2[g];
#pragma unroll
    for (int j = 0; j < F; ++j)
        o += hsm[lp][j] * w2[j * F + g];

    float* orow = out + ((size_t)b * npoints + pt) * F;
    orow[g] = (g < 3) ? row[lp][g] : o;
}

// ---------------------------------------------------------------------------
// Launch
// ---------------------------------------------------------------------------
extern "C" void kernel_launch(void* const* d_in, const int* in_sizes, int n_in_cnt,
                              void* d_out, int out_size)
{
    (void)in_sizes; (void)n_in_cnt; (void)out_size;

    const float* pts  = (const float*)d_in[0];
    const float* w1_1 = (const float*)d_in[1];
    const float* b1_1 = (const float*)d_in[2];
    const float* w2_1 = (const float*)d_in[3];
    const float* b2_1 = (const float*)d_in[4];
    const float* w1_2 = (const float*)d_in[5];
    const float* b1_2 = (const float*)d_in[6];
    const float* w2_2 = (const float*)d_in[7];
    const float* b2_2 = (const float*)d_in[8];
    const float* w1_3 = (const float*)d_in[9];
    const float* b1_3 = (const float*)d_in[10];
    const float* w2_3 = (const float*)d_in[11];
    const float* b2_3 = (const float*)d_in[12];
    const float* w1_4 = (const float*)d_in[13];
    const float* b1_4 = (const float*)d_in[14];
    const float* w2_4 = (const float*)d_in[15];
    const float* b2_4 = (const float*)d_in[16];

    float* out = (float*)d_out;
    const int B = 8;
    float* f1 = out;                        // [8,4096,16]
    float* f2 = out + 8 * 4096 * 16;        // [8,2048,32]
    float* f3 = f2 + 8 * 2048 * 32;         // [8,1024,64]
    float* f4 = f3 + 8 * 1024 * 64;         // [8, 512,128]

    static int*    idx_buf = nullptr;
    static float4* sort_buf = nullptr;
    if (!idx_buf)  cudaGetSymbolAddress((void**)&idx_buf,  g_fps_idx);
    if (!sort_buf) cudaGetSymbolAddress((void**)&sort_buf, g_sorted);

    static bool attr_done = false;
    if (!attr_done) {
        cudaFuncSetAttribute(fps_kernel<8192, 16>,
                             cudaFuncAttributeMaxDynamicSharedMemorySize, 8192 * 16);
        cudaFuncSetAttribute(fps_kernel<4096, 8>,
                             cudaFuncAttributeMaxDynamicSharedMemorySize, 4096 * 16);
        cudaFuncSetAttribute(fps_kernel<2048, 4>,
                             cudaFuncAttributeMaxDynamicSharedMemorySize, 2048 * 16);
        cudaFuncSetAttribute(fps_kernel<1024, 2>,
                             cudaFuncAttributeMaxDynamicSharedMemorySize, 1024 * 16);
        attr_done = true;
    }

    // Slot shim: keeps ncu's fixed capture index on the level-2 FPS launch.
    probe_align_kernel<<<1, 32>>>();

    // ---- Level 1: 8192 -> 4096, C=3 (repeat to 6), F=16 ----
    fps_kernel<8192, 16><<<B, 512, 8192 * 16>>>(pts, 3, 4096, idx_buf, sort_buf);
    mlp_kernel<3, 16, true><<<(B * 4096) / 16, 256>>>(
        pts, idx_buf, w1_1, b1_1, w2_1, b2_1, f1, 8192, 4096);

    // ---- Level 2: 4096 -> 2048, C=16, F=32 ----
    fps_kernel<4096, 8><<<B, 512, 4096 * 16>>>(f1, 16, 2048, idx_buf, sort_buf);
    mlp_kernel<16, 32, false><<<(B * 2048) / 8, 256>>>(
        f1, idx_buf, w1_2, b1_2, w2_2, b2_2, f2, 4096, 2048);

    // ---- Level 3: 2048 -> 1024, C=32, F=64 ----
    fps_kernel<2048, 4><<<B, 512, 2048 * 16>>>(f2, 32, 1024, idx_buf, sort_buf);
    mlp_kernel<32, 64, false><<<(B * 1024) / 4, 256>>>(
        f2, idx_buf, w1_3, b1_3, w2_3, b2_3, f3, 2048, 1024);

    // ---- Level 4: 1024 -> 512, C=64, F=128 ----
    fps_kernel<1024, 2><<<B, 512, 1024 * 16>>>(f3, 64, 512, idx_buf, sort_buf);
    mlp_kernel<64, 128, false><<<(B * 512) / 2, 256>>>(
        f3, idx_buf, w1_4, b1_4, w2_4, b2_4, f4, 1024, 512);
}

// round 12
// speedup vs baseline: 2.8858x; 1.5837x over previous
#include <cuda_runtime.h>
#include <cstdint>

// ---------------------------------------------------------------------------
// Scratch
// ---------------------------------------------------------------------------
__device__ int    g_fps_idx[8 * 4096];
__device__ float4 g_sorted[8 * 8192];     // per-batch spatially sorted points

typedef unsigned long long u64;

// Packed f32x2 add (per-lane IEEE rn — proven bitwise == scalar FADD in R6)
__device__ __forceinline__ u64 pack2(float a, float b) {
    u64 r; asm("mov.b64 %0, {%1, %2};" : "=l"(r) : "f"(a), "f"(b)); return r;
}
__device__ __forceinline__ void unpack2(u64 v, float& a, float& b) {
    asm("mov.b64 {%0, %1}, %2;" : "=f"(a), "=f"(b) : "l"(v));
}
__device__ __forceinline__ u64 add2(u64 a, u64 b) {
    u64 r; asm("add.rn.f32x2 %0, %1, %2;" : "=l"(r) : "l"(a), "l"(b)); return r;
}

// 8x8x8 Morton cell over [-4, 4]
__device__ __forceinline__ int cell_of(float x, float y, float z) {
    int cx = min(max((int)(x + 4.0f), 0), 7);
    int cy = min(max((int)(y + 4.0f), 0), 7);
    int cz = min(max((int)(z + 4.0f), 0), 7);
    return (cx & 1) | ((cy & 1) << 1) | ((cz & 1) << 2)
         | (((cx >> 1) & 1) << 3) | (((cy >> 1) & 1) << 4) | (((cz >> 1) & 1) << 5)
         | ((cx >> 2) << 6) | ((cy >> 2) << 7) | ((cz >> 2) << 8);
}

// Dummy kernel: three of these shift ncu's fixed capture slot (launch index
// 3) onto the level-1 FPS kernel.
__global__ void probe_align_kernel() {}

// ---------------------------------------------------------------------------
// FPS, 512 threads (16 warps) per batch — bit-proven R11 kernel, now only
// used for level 1 (8192 -> 4096).
//
// NESTED-FPS THEOREM (why levels 2-4 need no FPS): each level's xyz equals
// the gathered rows' xyz, and gathered row order == FPS pick order. By
// induction the sub-level FPS d-array is the bitwise restriction of the
// parent's (same pivots, same fminf chain), the parent's pick k lies in the
// subset and is its argmax, and all tied candidates are unselected points
// with gathered position > k — so jnp.argmax (first occurrence) returns
// position k. Hence idx = arange(npoints) for levels 2-4, bitwise.
// ---------------------------------------------------------------------------
template <int N, int K>
__global__ __launch_bounds__(512, 1)
void fps_kernel(const float* __restrict__ pts, int C, int npoints,
                int* __restrict__ idx_out, float4* __restrict__ sorted_g)
{
    constexpr int T  = 512;                   // threads
    constexpr int NW = 16;                    // warps

    extern __shared__ float4 sxyz[];          // N entries, ORIGINAL order
    __shared__ u64 rkey[2][NW];               // packed (valbits<<32)|comp
    __shared__ int hist[512];
    __shared__ int offs[512];

    const int b    = blockIdx.x;
    const int t    = threadIdx.x;
    const int lane = t & 31;
    const int wid  = t >> 5;

    const float* base = pts + (size_t)b * N * C;
    float4* sorted = sorted_g + (size_t)b * N;

    // ---- load orig-order copy + cell histogram ----
    hist[t] = 0;
    __syncthreads();
#pragma unroll
    for (int k = 0; k < K; ++k) {
        int i = t + k * T;
        const float* r = base + (size_t)i * C;
        float xx = r[0], yy = r[1], zz = r[2];
        sxyz[i] = make_float4(xx, yy, zz, 0.f);
        atomicAdd(&hist[cell_of(xx, yy, zz)], 1);
    }
    __syncthreads();
    if (t == 0) {
        int s = 0;
        for (int c = 0; c < 512; ++c) { offs[c] = s; s += hist[c]; }
    }
    __syncthreads();
#pragma unroll
    for (int k = 0; k < K; ++k) {
        int i = t + k * T;
        float4 q = sxyz[i];
        int pos = atomicAdd(&offs[cell_of(q.x, q.y, q.z)], 1);
        sorted[pos] = make_float4(q.x, q.y, q.z, __int_as_float(i));
    }
    __syncthreads();

    // ---- load my sorted points ----
    float xr[K], yr[K], zr[K], d[K];
    unsigned comp[K];                         // 0xFFFFFFFF - orig_idx
#pragma unroll
    for (int k = 0; k < K; ++k) {
        int slot = wid * (32 * K) + k * 32 + lane;
        float4 s = sorted[slot];
        xr[k] = s.x; yr[k] = s.y; zr[k] = s.z;
        comp[k] = 0xFFFFFFFFu - (unsigned)__float_as_int(s.w);
    }

    // ---- per-thread insertion sort by orig idx ascending (one-time) ----
    if constexpr (K >= 2) {
#pragma unroll
        for (int a = 1; a < K; ++a) {
#pragma unroll
            for (int c = a; c > 0; --c) {
                bool sw = comp[c] > comp[c - 1];
                float tf; unsigned tu;
                tf = sw ? xr[c] : xr[c - 1]; xr[c] = sw ? xr[c - 1] : xr[c]; xr[c - 1] = tf;
                tf = sw ? yr[c] : yr[c - 1]; yr[c] = sw ? yr[c - 1] : yr[c]; yr[c - 1] = tf;
                tf = sw ? zr[c] : zr[c - 1]; zr[c] = sw ? zr[c - 1] : zr[c]; zr[c - 1] = tf;
                tu = sw ? comp[c] : comp[c - 1]; comp[c] = sw ? comp[c - 1] : comp[c]; comp[c - 1] = tu;
            }
        }
    }

    // ---- per-warp bbox ----
    float mnx = 1e30f, mny = 1e30f, mnz = 1e30f;
    float mxx = -1e30f, mxy = -1e30f, mxz = -1e30f;
#pragma unroll
    for (int k = 0; k < K; ++k) {
        mnx = fminf(mnx, xr[k]); mxx = fmaxf(mxx, xr[k]);
        mny = fminf(mny, yr[k]); mxy = fmaxf(mxy, yr[k]);
        mnz = fminf(mnz, zr[k]); mxz = fmaxf(mxz, zr[k]);
    }
#pragma unroll
    for (int o = 16; o > 0; o >>= 1) {
        mnx = fminf(mnx, __shfl_xor_sync(0xffffffffu, mnx, o));
        mny = fminf(mny, __shfl_xor_sync(0xffffffffu, mny, o));
        mnz = fminf(mnz, __shfl_xor_sync(0xffffffffu, mnz, o));
        mxx = fmaxf(mxx, __shfl_xor_sync(0xffffffffu, mxx, o));
        mxy = fmaxf(mxy, __shfl_xor_sync(0xffffffffu, mxy, o));
        mxz = fmaxf(mxz, __shfl_xor_sync(0xffffffffu, mxz, o));
    }

    // ---- packed coord registers ----
    constexpr int KP = (K >= 2) ? K / 2 : 1;
    u64 xp[KP], yp[KP], zp[KP];
    if constexpr (K >= 2) {
#pragma unroll
        for (int k2 = 0; k2 < KP; ++k2) {
            xp[k2] = pack2(xr[2 * k2], xr[2 * k2 + 1]);
            yp[k2] = pack2(yr[2 * k2], yr[2 * k2 + 1]);
            zp[k2] = pack2(zr[2 * k2], zr[2 * k2 + 1]);
        }
    }

    if (t == 0) idx_out[b * npoints] = 0;

    // ---- initial distances to point 0 + argmax ----
    float    bv = -1.0f;
    unsigned bc = 0;
    {
        float4 q = sxyz[0];
        float px = q.x, py = q.y, pz = q.z;
#pragma unroll
        for (int k = 0; k < K; ++k) {
            float dx = xr[k] - px, dy = yr[k] - py, dz = zr[k] - pz;
            d[k] = dx * dx + dy * dy + dz * dz;
            if (d[k] > bv) { bv = d[k]; bc = comp[k]; }
        }
    }
    unsigned cm, ccomp;
    {
        unsigned ub = __float_as_uint(bv);
        cm = __reduce_max_sync(0xffffffffu, ub);
        unsigned cand = (ub == cm) ? bc : 0u;
        ccomp = __reduce_max_sync(0xffffffffu, cand);
    }

    for (int it = 1; it < npoints; ++it) {
        const int p = it & 1;
        if (lane == 0) rkey[p][wid] = ((u64)cm << 32) | (u64)ccomp;
        __syncthreads();

        // stage 2: reduce the 16 warp keys
        u64 kk = rkey[p][lane & (NW - 1)];
        unsigned vw = (unsigned)(kk >> 32);
        unsigned iw = (unsigned)kk;
        unsigned m2 = __reduce_max_sync(0xffffffffu, vw);
        unsigned c2 = (vw == m2) ? iw : 0u;
        unsigned comp2 = __reduce_max_sync(0xffffffffu, c2);
        int bsel = (int)(0xFFFFFFFFu - comp2);       // ORIGINAL index

        if (t == 0) idx_out[b * npoints + it] = bsel;

        float4 q = sxyz[bsel];
        float px = q.x, py = q.y, pz = q.z;

        // warp-uniform exact bbox skip test
        float ax = fmaxf(fmaxf(mnx - px, px - mxx), 0.f);
        float ay = fmaxf(fmaxf(mny - py, py - mxy), 0.f);
        float az = fmaxf(fmaxf(mnz - pz, pz - mxz), 0.f);
        float mind2 = ax * ax + ay * ay + az * az;

        if (mind2 < __uint_as_float(cm)) {
            bv = -1.0f; bc = 0;
            if constexpr (K >= 2) {
                const u64 nxp = pack2(-px, -px);
                const u64 nyp = pack2(-py, -py);
                const u64 nzp = pack2(-pz, -pz);
#pragma unroll
                for (int k2 = 0; k2 < KP; ++k2) {
                    float dx0, dx1, dy0, dy1, dz0, dz1;
                    unpack2(add2(xp[k2], nxp), dx0, dx1);
                    unpack2(add2(yp[k2], nyp), dy0, dy1);
                    unpack2(add2(zp[k2], nzp), dz0, dz1);
                    float nd0 = dx0 * dx0 + dy0 * dy0 + dz0 * dz0;
                    float nd1 = dx1 * dx1 + dy1 * dy1 + dz1 * dz1;
                    float dk0 = fminf(d[2 * k2],     nd0);
                    float dk1 = fminf(d[2 * k2 + 1], nd1);
                    d[2 * k2]     = dk0;
                    d[2 * k2 + 1] = dk1;
                    if (dk0 > bv) { bv = dk0; bc = comp[2 * k2]; }
                    if (dk1 > bv) { bv = dk1; bc = comp[2 * k2 + 1]; }
                }
            } else {
                float dx = xr[0] - px, dy = yr[0] - py, dz = zr[0] - pz;
                float nd = dx * dx + dy * dy + dz * dz;
                float dk = fminf(d[0], nd);
                d[0] = dk; bv = dk; bc = comp[0];
            }
            unsigned ub = __float_as_uint(bv);
            cm = __reduce_max_sync(0xffffffffu, ub);
            unsigned cand = (ub == cm) ? bc : 0u;
            ccomp = __reduce_max_sync(0xffffffffu, cand);
        }
        // else: skip — d unchanged, cached (cm, ccomp) still exact
    }
}

// ---------------------------------------------------------------------------
// Gather + pointwise 2-layer MLP + output assembly.
// IDENT=true: downsample row index == output row index (nested-FPS theorem;
// levels 2-4 take the first `npoints` rows of the previous output).
// ---------------------------------------------------------------------------
template <int CPREV, int F, bool REPEAT, bool IDENT>
__global__ __launch_bounds__(256)
void mlp_kernel(const float* __restrict__ in, const int* __restrict__ idx,
                const float* __restrict__ w1, const float* __restrict__ b1,
                const float* __restrict__ w2, const float* __restrict__ b2,
                float* __restrict__ out, int n_in, int npoints)
{
    constexpr int PPB = 256 / F;
    constexpr int CIN = REPEAT ? 2 * CPREV : CPREV;

    __shared__ float row[PPB][CPREV];
    __shared__ float hsm[PPB][F];

    const int t  = threadIdx.x;
    const int lp = t / F;
    const int g  = t % F;
    const int gp = blockIdx.x * PPB + lp;
    const int b  = gp / npoints;
    const int pt = gp % npoints;

    const int src = IDENT ? pt : idx[b * npoints + pt];
    const float* r = in + ((size_t)b * n_in + src) * CPREV;
    if (g < CPREV) row[lp][g] = r[g];
    __syncthreads();

    float acc = b1[g];
#pragma unroll
    for (int c = 0; c < CIN; ++c)
        acc += row[lp][c % CPREV] * w1[c * F + g];
    hsm[lp][g] = fmaxf(acc, 0.0f);
    __syncthreads();

    float o = b2[g];
#pragma unroll
    for (int j = 0; j < F; ++j)
        o += hsm[lp][j] * w2[j * F + g];

    float* orow = out + ((size_t)b * npoints + pt) * F;
    orow[g] = (g < 3) ? row[lp][g] : o;
}

// ---------------------------------------------------------------------------
// Launch
// ---------------------------------------------------------------------------
extern "C" void kernel_launch(void* const* d_in, const int* in_sizes, int n_in_cnt,
                              void* d_out, int out_size)
{
    (void)in_sizes; (void)n_in_cnt; (void)out_size;

    const float* pts  = (const float*)d_in[0];
    const float* w1_1 = (const float*)d_in[1];
    const float* b1_1 = (const float*)d_in[2];
    const float* w2_1 = (const float*)d_in[3];
    const float* b2_1 = (const float*)d_in[4];
    const float* w1_2 = (const float*)d_in[5];
    const float* b1_2 = (const float*)d_in[6];
    const float* w2_2 = (const float*)d_in[7];
    const float* b2_2 = (const float*)d_in[8];
    const float* w1_3 = (const float*)d_in[9];
    const float* b1_3 = (const float*)d_in[10];
    const float* w2_3 = (const float*)d_in[11];
    const float* b2_3 = (const float*)d_in[12];
    const float* w1_4 = (const float*)d_in[13];
    const float* b1_4 = (const float*)d_in[14];
    const float* w2_4 = (const float*)d_in[15];
    const float* b2_4 = (const float*)d_in[16];

    float* out = (float*)d_out;
    const int B = 8;
    float* f1 = out;                        // [8,4096,16]
    float* f2 = out + 8 * 4096 * 16;        // [8,2048,32]
    float* f3 = f2 + 8 * 2048 * 32;         // [8,1024,64]
    float* f4 = f3 + 8 * 1024 * 64;         // [8, 512,128]

    static int*    idx_buf = nullptr;
    static float4* sort_buf = nullptr;
    if (!idx_buf)  cudaGetSymbolAddress((void**)&idx_buf,  g_fps_idx);
    if (!sort_buf) cudaGetSymbolAddress((void**)&sort_buf, g_sorted);

    static bool attr_done = false;
    if (!attr_done) {
        cudaFuncSetAttribute(fps_kernel<8192, 16>,
                             cudaFuncAttributeMaxDynamicSharedMemorySize, 8192 * 16);
        attr_done = true;
    }

    // Slot shims: launch indices 0-2, so ncu's fixed capture slot (index 3)
    // lands on the level-1 FPS kernel.
    probe_align_kernel<<<1, 32>>>();
    probe_align_kernel<<<1, 32>>>();
    probe_align_kernel<<<1, 32>>>();

    // ---- Level 1: 8192 -> 4096 — the ONLY FPS run ----
    fps_kernel<8192, 16><<<B, 512, 8192 * 16>>>(pts, 3, 4096, idx_buf, sort_buf);
    mlp_kernel<3, 16, true, false><<<(B * 4096) / 16, 256>>>(
        pts, idx_buf, w1_1, b1_1, w2_1, b2_1, f1, 8192, 4096);

    // ---- Levels 2-4: nested-FPS theorem -> identity downsample ----
    mlp_kernel<16, 32, false, true><<<(B * 2048) / 8, 256>>>(
        f1, idx_buf, w1_2, b1_2, w2_2, b2_2, f2, 4096, 2048);

    mlp_kernel<32, 64, false, true><<<(B * 1024) / 4, 256>>>(
        f2, idx_buf, w1_3, b1_3, w2_3, b2_3, f3, 2048, 1024);

    mlp_kernel<64, 128, false, true><<<(B * 512) / 2, 256>>>(
        f3, idx_buf, w1_4, b1_4, w2_4, b2_4, f4, 1024, 512);
}